// round 5
// baseline (speedup 1.0000x reference)
#include <cuda_runtime.h>
#include <cuda_bf16.h>

// Problem constants
#define BV     32000   // vocab
#define EE     256     // embed dim
#define HH     512     // hidden
#define SS     128     // enc seq len
#define TT     64      // dec len
#define BB     32      // batch
#define NSTEP  63      // T_DEC - 1
#define H3     1536    // 3*H
#define OUT_PRED (64512000LL)   // B * NSTEP * V

// ---------------- scratch (device globals; no allocation allowed) ----------
// g_encCat[(b*128+s)][0:512)    = enc @ W1        (attention score input)
// g_encCat[(b*128+s)][512:2048) = enc @ Wx_top    (ctx contribution to gx)
__device__ float g_encCat[4096 * 2048];           // 33.5 MB
__device__ float g_gxemb [NSTEP * BB * H3];       // emb@Wx_bot + b_g, all steps
__device__ float g_h     [NSTEP * BB * HH];       // h_t for all steps
__device__ float g_hW2   [BB * HH];
__device__ float g_ghzr  [BB * 1024];
__device__ float g_score [BB * SS];
__device__ float g_z     [BB * HH];
__device__ float g_rh    [BB * HH];
__device__ float g_gx3   [BB * HH];

// ---------------- helpers ---------------------------------------------------
__device__ __forceinline__ unsigned long long dup2(float b) {
    unsigned long long r;
    unsigned int u = __float_as_uint(b);
    asm("mov.b64 %0, {%1, %1};" : "=l"(r) : "r"(u));
    return r;
}
__device__ __forceinline__ void fma2(unsigned long long& d,
                                     unsigned long long a,
                                     unsigned long long b) {
    asm("fma.rn.f32x2 %0, %1, %2, %3;" : "=l"(d) : "l"(a), "l"(b), "l"(d));
}
// exact-identity tanh on fast exp: abs err ~1e-7, 2 MUFU ops
__device__ __forceinline__ float fast_tanh(float x) {
    float e = __expf(2.0f * x);
    return 1.0f - 2.0f / (e + 1.0f);
}
__device__ __forceinline__ float fast_sig(float x) {
    return 1.0f / (1.0f + __expf(-x));
}

// ---------------- generic 128x128 tiled fp32 GEMM with f32x2 FMAs -----------
// MODE 0: C=g_encCat : A=enc(4096x512),        B=[W1 | Wx_top](512x2048)
// MODE 1: C=g_gxemb  : A=emb[tok(m)](2016x256), B=Wx_bot(256x1536), +b_g
// MODE 2: C=preds    : A=g_h(2016x512),         B=Wo(512x32000), +bo, scatter
template<int MODE>
__global__ __launch_bounds__(256, 2)
void gemm_k(const float* __restrict__ A,  const float* __restrict__ W1,
            const float* __restrict__ Wx, const float* __restrict__ Wo,
            const float* __restrict__ bias,
            const int*   __restrict__ dinp, const int* __restrict__ dtgt,
            const float* __restrict__ emb, float* __restrict__ C,
            int M, int K)
{
    __shared__ __align__(16) float As[16][132];
    __shared__ __align__(16) float Bs[16][132];

    const int tid = threadIdx.x;
    const int tx = tid & 15;   // col group: cols tx*4..+3 and 64+tx*4..+3
    const int ty = tid >> 4;   // row group: rows ty*8..+7
    const int bn = blockIdx.x, bm = blockIdx.y;

    unsigned long long acc[4][8];
#pragma unroll
    for (int i = 0; i < 4; i++)
#pragma unroll
        for (int j = 0; j < 8; j++) acc[i][j] = 0ULL;

    const int nTiles = K >> 4;
    for (int kt = 0; kt < nTiles; ++kt) {
#pragma unroll
        for (int q = 0; q < 2; q++) {
            int l = tid * 2 + q;          // 0..511
            // ---- A tile: 128 rows x 16 k, stored transposed As[k][m]
            int r = l >> 2;               // 0..127
            int cseg = l & 3;             // 0..3 (4 cols each)
            int rowg = bm * 128 + r; if (rowg > M - 1) rowg = M - 1;
            const float* ap;
            if (MODE == 1) {
                int t = rowg >> 5, b = rowg & 31;
                int tok = (t == 0) ? dinp[b] : dtgt[b * TT + t];
                ap = emb + (long long)tok * EE;
            } else if (MODE == 2) {
                ap = g_h + (long long)rowg * HH;
            } else {
                ap = A + (long long)rowg * K;
            }
            float4 v = *reinterpret_cast<const float4*>(ap + kt * 16 + cseg * 4);
            As[cseg * 4 + 0][r] = v.x; As[cseg * 4 + 1][r] = v.y;
            As[cseg * 4 + 2][r] = v.z; As[cseg * 4 + 3][r] = v.w;
            // ---- B tile: 16 k-rows x 128 cols
            int kr = l >> 5;              // 0..15
            int nseg = l & 31;            // 0..31
            int kg = kt * 16 + kr;
            int n = bn * 128 + nseg * 4;
            const float* bp;
            if (MODE == 0) {
                bp = (n < 512) ? (W1 + (long long)kg * 512 + n)
                               : (Wx + (long long)kg * H3 + (n - 512));
            } else if (MODE == 1) {
                bp = Wx + (long long)(512 + kg) * H3 + n;
            } else {
                bp = Wo + (long long)kg * BV + n;
            }
            *reinterpret_cast<float4*>(&Bs[kr][nseg * 4]) =
                *reinterpret_cast<const float4*>(bp);
        }
        __syncthreads();
#pragma unroll
        for (int k = 0; k < 16; k++) {
            const unsigned long long* arow =
                reinterpret_cast<const unsigned long long*>(&As[k][0]);
            unsigned long long a0 = arow[ty * 4 + 0];
            unsigned long long a1 = arow[ty * 4 + 1];
            unsigned long long a2 = arow[ty * 4 + 2];
            unsigned long long a3 = arow[ty * 4 + 3];
            float4 b0 = *reinterpret_cast<const float4*>(&Bs[k][tx * 4]);
            float4 b1 = *reinterpret_cast<const float4*>(&Bs[k][64 + tx * 4]);
            float bf[8] = {b0.x, b0.y, b0.z, b0.w, b1.x, b1.y, b1.z, b1.w};
#pragma unroll
            for (int j = 0; j < 8; j++) {
                unsigned long long dj = dup2(bf[j]);
                fma2(acc[0][j], a0, dj);
                fma2(acc[1][j], a1, dj);
                fma2(acc[2][j], a2, dj);
                fma2(acc[3][j], a3, dj);
            }
        }
        __syncthreads();
    }

    // ---- epilogue
    const int nA = bn * 128 + tx * 4;
    const int nB = nA + 64;
#pragma unroll
    for (int i2 = 0; i2 < 4; i2++) {
#pragma unroll
        for (int p = 0; p < 2; p++) {
            int m = bm * 128 + ty * 8 + i2 * 2 + p;
            if (m >= M) continue;
            float vals[8];
#pragma unroll
            for (int j = 0; j < 8; j++) {
                unsigned long long u = acc[i2][j];
                unsigned int w = (p == 0) ? (unsigned int)u
                                          : (unsigned int)(u >> 32);
                vals[j] = __uint_as_float(w);
            }
            if (MODE == 0) {
                float* cp = g_encCat + (long long)m * 2048;
                *reinterpret_cast<float4*>(cp + nA) =
                    make_float4(vals[0], vals[1], vals[2], vals[3]);
                *reinterpret_cast<float4*>(cp + nB) =
                    make_float4(vals[4], vals[5], vals[6], vals[7]);
            } else if (MODE == 1) {
                float* cp = g_gxemb + (long long)m * H3;
                float4 ba = *reinterpret_cast<const float4*>(bias + nA);
                float4 bb = *reinterpret_cast<const float4*>(bias + nB);
                *reinterpret_cast<float4*>(cp + nA) =
                    make_float4(vals[0] + ba.x, vals[1] + ba.y,
                                vals[2] + ba.z, vals[3] + ba.w);
                *reinterpret_cast<float4*>(cp + nB) =
                    make_float4(vals[4] + bb.x, vals[5] + bb.y,
                                vals[6] + bb.z, vals[7] + bb.w);
            } else {
                int t = m >> 5, b = m & 31;   // m = t*32 + b
                float* cp = C + (long long)b * (NSTEP * (long long)BV)
                              + (long long)t * BV;
                float4 ba = *reinterpret_cast<const float4*>(bias + nA);
                float4 bb = *reinterpret_cast<const float4*>(bias + nB);
                *reinterpret_cast<float4*>(cp + nA) =
                    make_float4(vals[0] + ba.x, vals[1] + ba.y,
                                vals[2] + ba.z, vals[3] + ba.w);
                *reinterpret_cast<float4*>(cp + nB) =
                    make_float4(vals[4] + bb.x, vals[5] + bb.y,
                                vals[6] + bb.z, vals[7] + bb.w);
            }
        }
    }
}

// ---------------- per-step kernels ------------------------------------------
// S1: hW2[b][0:512] = h_prev @ W2 ; ghzr[b][0:1024] = h_prev @ Wh[:, :1024]
__global__ void k_hproj(const float* __restrict__ dec_hidden,
                        const float* __restrict__ W2,
                        const float* __restrict__ Wh, int t)
{
    int b = blockIdx.y;
    int c = blockIdx.x * 128 + threadIdx.x;  // 0..1535
    const float* h = (t == 0) ? (dec_hidden + b * HH)
                              : (g_h + ((long long)(t - 1) * BB + b) * HH);
    __shared__ float hs[HH];
    for (int i = threadIdx.x; i < HH; i += 128) hs[i] = h[i];
    __syncthreads();
    const float* wcol; long long ldw;
    if (c < 512) { wcol = W2 + c;         ldw = 512; }
    else         { wcol = Wh + (c - 512); ldw = H3;  }
    float a0 = 0.f, a1 = 0.f, a2 = 0.f, a3 = 0.f;
    for (int k = 0; k < HH; k += 4) {
        a0 += hs[k + 0] * wcol[(k + 0) * ldw];
        a1 += hs[k + 1] * wcol[(k + 1) * ldw];
        a2 += hs[k + 2] * wcol[(k + 2) * ldw];
        a3 += hs[k + 3] * wcol[(k + 3) * ldw];
    }
    float r = (a0 + a1) + (a2 + a3);
    if (c < 512) g_hW2[b * 512 + c] = r;
    else         g_ghzr[b * 1024 + (c - 512)] = r;
}

// S2: score[b][s] = sum_a tanh(encW1[b,s,a] + hW2[b,a]) * v_a[a]
__global__ void k_score(const float* __restrict__ v_a)
{
    int b = blockIdx.y;
    int warp = threadIdx.x >> 5, lane = threadIdx.x & 31;
    int s = blockIdx.x * 8 + warp;
    __shared__ float hv[HH], vv[HH];
    for (int i = threadIdx.x; i < HH; i += 256) {
        hv[i] = g_hW2[b * HH + i];
        vv[i] = v_a[i];
    }
    __syncthreads();
    const float* e = g_encCat + ((long long)b * SS + s) * 2048;
    float sum = 0.f;
#pragma unroll
    for (int i = 0; i < 16; i++) {
        int a = i * 32 + lane;
        sum += fast_tanh(e[a] + hv[a]) * vv[a];
    }
#pragma unroll
    for (int o = 16; o > 0; o >>= 1) sum += __shfl_xor_sync(0xffffffffu, sum, o);
    if (lane == 0) g_score[b * SS + s] = sum;
}

// S3: softmax over s; gx = sum_s attn*encWx + gxemb; z, r*h, gx3
__global__ void k_attnmix(const float* __restrict__ dec_hidden, int t)
{
    int b = blockIdx.y;
    int tidx = threadIdx.x;                  // 0..127
    int j = blockIdx.x * 128 + tidx;         // 0..1535
    __shared__ float attn[SS];
    __shared__ float red[SS];

    float sc = g_score[b * SS + tidx];
    red[tidx] = sc; __syncthreads();
    for (int o = 64; o > 0; o >>= 1) {
        if (tidx < o) red[tidx] = fmaxf(red[tidx], red[tidx + o]);
        __syncthreads();
    }
    float mx = red[0]; __syncthreads();
    float ex = __expf(sc - mx);
    red[tidx] = ex; __syncthreads();
    for (int o = 64; o > 0; o >>= 1) {
        if (tidx < o) red[tidx] += red[tidx + o];
        __syncthreads();
    }
    attn[tidx] = ex / red[0];
    __syncthreads();

    const float* base = g_encCat + (long long)b * SS * 2048 + 512 + j;
    float acc = 0.f;
#pragma unroll 8
    for (int s = 0; s < SS; s++) acc += attn[s] * base[(long long)s * 2048];
    acc += g_gxemb[((long long)t * BB + b) * H3 + j];

    const float* h = (t == 0) ? (dec_hidden + b * HH)
                              : (g_h + ((long long)(t - 1) * BB + b) * HH);
    if (j < 512) {
        g_z[b * HH + j] = fast_sig(acc + g_ghzr[b * 1024 + j]);
    } else if (j < 1024) {
        int jj = j - 512;
        float rr = fast_sig(acc + g_ghzr[b * 1024 + j]);
        g_rh[b * HH + jj] = rr * h[jj];
    } else {
        g_gx3[b * HH + (j - 1024)] = acc;
    }
}

// S4: hh = tanh(gx3 + rh @ Wh[:,1024:]); h_new = z*h + (1-z)*hh
__global__ void k_hh(const float* __restrict__ dec_hidden,
                     const float* __restrict__ Wh, int t)
{
    int b = blockIdx.y;
    int j = blockIdx.x * 128 + threadIdx.x;  // 0..511
    __shared__ float rs[HH];
    for (int i = threadIdx.x; i < HH; i += 128) rs[i] = g_rh[b * HH + i];
    __syncthreads();
    const float* wc = Wh + 1024 + j;
    float a0 = 0.f, a1 = 0.f, a2 = 0.f, a3 = 0.f;
    for (int k = 0; k < HH; k += 4) {
        a0 += rs[k + 0] * wc[(long long)(k + 0) * H3];
        a1 += rs[k + 1] * wc[(long long)(k + 1) * H3];
        a2 += rs[k + 2] * wc[(long long)(k + 2) * H3];
        a3 += rs[k + 3] * wc[(long long)(k + 3) * H3];
    }
    float hh = fast_tanh(g_gx3[b * HH + j] + (a0 + a1) + (a2 + a3));
    const float* h = (t == 0) ? (dec_hidden + b * HH)
                              : (g_h + ((long long)(t - 1) * BB + b) * HH);
    float zz = g_z[b * HH + j];
    g_h[((long long)t * BB + b) * HH + j] = zz * h[j] + (1.0f - zz) * hh;
}

// final hidden state copy: h_fin = h at t = NSTEP-1
__global__ void k_copyh(float* __restrict__ out)
{
    int i = blockIdx.x * 256 + threadIdx.x;  // 0..16383
    out[i] = g_h[(long long)(NSTEP - 1) * BB * HH + i];
}

extern "C" void kernel_launch(void* const* d_in, const int* in_sizes, int n_in,
                              void* d_out, int out_size)
{
    const int*   dec_input  = (const int*)  d_in[0];
    const float* dec_hidden = (const float*)d_in[1];
    const float* enc_output = (const float*)d_in[2];
    const int*   dec_target = (const int*)  d_in[3];
    const float* embedding  = (const float*)d_in[4];
    const float* W1  = (const float*)d_in[5];
    const float* W2  = (const float*)d_in[6];
    const float* v_a = (const float*)d_in[7];
    const float* Wx  = (const float*)d_in[8];
    const float* Wh  = (const float*)d_in[9];
    const float* b_g = (const float*)d_in[10];
    const float* Wo  = (const float*)d_in[11];
    const float* bo  = (const float*)d_in[12];
    float* out = (float*)d_out;

    // Precompute 1: encCat = enc @ [W1 | Wx_top]   (4096 x 2048, K=512)
    gemm_k<0><<<dim3(16, 32), 256>>>(enc_output, W1, Wx, nullptr, nullptr,
                                     nullptr, nullptr, nullptr, nullptr,
                                     4096, 512);
    // Precompute 2: gxemb = emb[tok] @ Wx_bot + b_g (2016 x 1536, K=256)
    gemm_k<1><<<dim3(12, 16), 256>>>(nullptr, nullptr, Wx, nullptr, b_g,
                                     dec_input, dec_target, embedding, nullptr,
                                     2016, 256);
    // Recurrence: 63 steps x 4 kernels
    for (int t = 0; t < NSTEP; t++) {
        k_hproj  <<<dim3(12, 32), 128>>>(dec_hidden, W2, Wh, t);
        k_score  <<<dim3(16, 32), 256>>>(v_a);
        k_attnmix<<<dim3(12, 32), 128>>>(dec_hidden, t);
        k_hh     <<<dim3(4, 32), 128>>>(dec_hidden, Wh, t);
    }
    // Deferred pred GEMM: (2016 x 32000, K=512), scattered to (b, t, v)
    gemm_k<2><<<dim3(250, 16), 256>>>(nullptr, nullptr, nullptr, Wo, bo,
                                      nullptr, nullptr, nullptr, out,
                                      2016, 512);
    // h_fin
    if ((long long)out_size >= OUT_PRED + BB * HH)
        k_copyh<<<64, 256>>>(out + OUT_PRED);
}